// round 1
// baseline (speedup 1.0000x reference)
#include <cuda_runtime.h>
#include <cstdint>

#define NN 8192
#define FD 10
#define HD 64
#define EMX 524288

// Scratch (static __device__ per allocation rules)
__device__ float g_h[2][NN * HD];
__device__ int g_cnt[NN];
__device__ int g_start[NN];
__device__ int g_fill[NN];
__device__ int g_csr[EMX];

// ---------------------------------------------------------------------------
// h0 = relu(features @ W_node + b_node)   [8192,10]@[10,64]
// one block (64 threads) per row
// ---------------------------------------------------------------------------
__global__ void k_node(const float* __restrict__ feat,
                       const float* __restrict__ Wn,
                       const float* __restrict__ bn) {
    int row = blockIdx.x;
    int t = threadIdx.x;
    __shared__ float f[FD];
    if (t < FD) f[t] = feat[row * FD + t];
    __syncthreads();
    float acc = bn[t];
#pragma unroll
    for (int k = 0; k < FD; k++) acc = fmaf(f[k], Wn[k * HD + t], acc);
    g_h[0][row * HD + t] = fmaxf(acc, 0.f);
}

// ---------------------------------------------------------------------------
// CSR build: count per dst -> exclusive scan -> fill src lists
// ---------------------------------------------------------------------------
__global__ void k_zero() {
    int i = blockIdx.x * blockDim.x + threadIdx.x;
    if (i < NN) g_cnt[i] = 0;
}

__global__ void k_count(const int* __restrict__ edges, int E) {
    int e = blockIdx.x * blockDim.x + threadIdx.x;
    if (e < E) atomicAdd(&g_cnt[edges[2 * e + 1]], 1);
}

// single block, 1024 threads, 8 counts each (8192 total)
__global__ void k_scan() {
    __shared__ int sd[1024];
    int t = threadIdx.x;
    int base = t * 8;
    int loc[8];
    int s = 0;
#pragma unroll
    for (int j = 0; j < 8; j++) { loc[j] = s; s += g_cnt[base + j]; }
    sd[t] = s;
    __syncthreads();
    for (int off = 1; off < 1024; off <<= 1) {
        int v = (t >= off) ? sd[t - off] : 0;
        __syncthreads();
        sd[t] += v;
        __syncthreads();
    }
    int excl = (t == 0) ? 0 : sd[t - 1];
#pragma unroll
    for (int j = 0; j < 8; j++) {
        int o = excl + loc[j];
        g_start[base + j] = o;
        g_fill[base + j] = o;
    }
}

__global__ void k_fill(const int* __restrict__ edges, int E) {
    int e = blockIdx.x * blockDim.x + threadIdx.x;
    if (e < E) {
        int dst = edges[2 * e + 1];
        int pos = atomicAdd(&g_fill[dst], 1);
        g_csr[pos] = edges[2 * e + 0];
    }
}

// ---------------------------------------------------------------------------
// Fused conv round: agg gather (CSR, L2-resident h) + (h+agg)@W_conv + relu
// one block (64 threads = one feature column each) per node; ping-pong buffers
// ---------------------------------------------------------------------------
__global__ void k_conv(int ib, int ob,
                       const float* __restrict__ Wc,
                       const float* __restrict__ bc) {
    const float* __restrict__ hin = g_h[ib];
    float* __restrict__ hout = g_h[ob];
    int i = blockIdx.x;
    int t = threadIdx.x;
    int s0 = g_start[i];
    int c = g_cnt[i];
    float a0 = 0.f, a1 = 0.f, a2 = 0.f, a3 = 0.f;
    int e = 0;
    for (; e + 4 <= c; e += 4) {
        int i0 = g_csr[s0 + e + 0];
        int i1 = g_csr[s0 + e + 1];
        int i2 = g_csr[s0 + e + 2];
        int i3 = g_csr[s0 + e + 3];
        a0 += hin[i0 * HD + t];
        a1 += hin[i1 * HD + t];
        a2 += hin[i2 * HD + t];
        a3 += hin[i3 * HD + t];
    }
    for (; e < c; e++) a0 += hin[g_csr[s0 + e] * HD + t];

    __shared__ float x[HD];
    x[t] = hin[i * HD + t] + ((a0 + a1) + (a2 + a3));
    __syncthreads();

    float acc = bc[t];
#pragma unroll
    for (int k = 0; k < HD; k++) acc = fmaf(x[k], Wc[k * HD + t], acc);
    hout[i * HD + t] = fmaxf(acc, 0.f);
}

// ---------------------------------------------------------------------------
// S = h @ h^T ; out[0] = S * m_i * m_j ; out[1] = S
// 128x128 block tile, K=64 in two 32-chunks, 8x8 per thread
// ---------------------------------------------------------------------------
__global__ __launch_bounds__(256, 2) void k_gemm(const int* __restrict__ nodes,
                                                 float* __restrict__ out) {
    const float* __restrict__ h = g_h[0];
    __shared__ float As[128][33];
    __shared__ float Bs[128][33];

    int tid = threadIdx.x;
    int tx = tid & 15;   // 0..15 -> cols tx*4 and 64+tx*4
    int ty = tid >> 4;   // 0..15 -> rows ty*4 and 64+ty*4
    int row0 = blockIdx.y * 128;
    int col0 = blockIdx.x * 128;

    float acc[8][8];
#pragma unroll
    for (int i = 0; i < 8; i++)
#pragma unroll
        for (int j = 0; j < 8; j++) acc[i][j] = 0.f;

    int lr = tid >> 3;  // 0..31
    int lc = tid & 7;   // 0..7

#pragma unroll
    for (int k0 = 0; k0 < HD; k0 += 32) {
#pragma unroll
        for (int p = 0; p < 4; p++) {
            int r = lr + p * 32;
            float4 va = *reinterpret_cast<const float4*>(
                &h[(size_t)(row0 + r) * HD + k0 + lc * 4]);
            As[r][lc * 4 + 0] = va.x;
            As[r][lc * 4 + 1] = va.y;
            As[r][lc * 4 + 2] = va.z;
            As[r][lc * 4 + 3] = va.w;
            float4 vb = *reinterpret_cast<const float4*>(
                &h[(size_t)(col0 + r) * HD + k0 + lc * 4]);
            Bs[r][lc * 4 + 0] = vb.x;
            Bs[r][lc * 4 + 1] = vb.y;
            Bs[r][lc * 4 + 2] = vb.z;
            Bs[r][lc * 4 + 3] = vb.w;
        }
        __syncthreads();
#pragma unroll
        for (int k = 0; k < 32; k++) {
            float a[8], b[8];
#pragma unroll
            for (int i = 0; i < 4; i++) {
                a[i] = As[ty * 4 + i][k];
                a[4 + i] = As[64 + ty * 4 + i][k];
            }
#pragma unroll
            for (int j = 0; j < 4; j++) {
                b[j] = Bs[tx * 4 + j][k];
                b[4 + j] = Bs[64 + tx * 4 + j][k];
            }
#pragma unroll
            for (int i = 0; i < 8; i++)
#pragma unroll
                for (int j = 0; j < 8; j++)
                    acc[i][j] = fmaf(a[i], b[j], acc[i][j]);
        }
        __syncthreads();
    }

    // masks
    float mr[8], mc[8];
#pragma unroll
    for (int i = 0; i < 8; i++) {
        int ri = (i < 4) ? (ty * 4 + i) : (64 + ty * 4 + (i - 4));
        mr[i] = (nodes[row0 + ri] == 2) ? 1.f : 0.f;
    }
#pragma unroll
    for (int j = 0; j < 8; j++) {
        int cj = (j < 4) ? (tx * 4 + j) : (64 + tx * 4 + (j - 4));
        mc[j] = (nodes[col0 + cj] == 2) ? 1.f : 0.f;
    }

    float* out_dep = out;                            // plane 0: function_deps
    float* out_sim = out + (size_t)NN * NN;          // plane 1: similarity

#pragma unroll
    for (int i = 0; i < 8; i++) {
        int ri = (i < 4) ? (ty * 4 + i) : (64 + ty * 4 + (i - 4));
        size_t base = (size_t)(row0 + ri) * NN + col0;
        float4 s0 = make_float4(acc[i][0], acc[i][1], acc[i][2], acc[i][3]);
        float4 s1 = make_float4(acc[i][4], acc[i][5], acc[i][6], acc[i][7]);
        *reinterpret_cast<float4*>(&out_sim[base + tx * 4]) = s0;
        *reinterpret_cast<float4*>(&out_sim[base + 64 + tx * 4]) = s1;
        float mi = mr[i];
        float4 d0 = make_float4(acc[i][0] * mi * mc[0], acc[i][1] * mi * mc[1],
                                acc[i][2] * mi * mc[2], acc[i][3] * mi * mc[3]);
        float4 d1 = make_float4(acc[i][4] * mi * mc[4], acc[i][5] * mi * mc[5],
                                acc[i][6] * mi * mc[6], acc[i][7] * mi * mc[7]);
        *reinterpret_cast<float4*>(&out_dep[base + tx * 4]) = d0;
        *reinterpret_cast<float4*>(&out_dep[base + 64 + tx * 4]) = d1;
    }
}

// ---------------------------------------------------------------------------
extern "C" void kernel_launch(void* const* d_in, const int* in_sizes, int n_in,
                              void* d_out, int out_size) {
    const float* feat = (const float*)d_in[0];
    const float* Wn   = (const float*)d_in[1];
    const float* bn   = (const float*)d_in[2];
    const float* Wc   = (const float*)d_in[3];
    const float* bc   = (const float*)d_in[4];
    const int* nodes  = (const int*)d_in[5];
    const int* edges  = (const int*)d_in[6];
    int E = in_sizes[6] / 2;
    float* out = (float*)d_out;

    // 1. node transform
    k_node<<<NN, 64>>>(feat, Wn, bn);

    // 2. CSR build (by dst)
    k_zero<<<(NN + 255) / 256, 256>>>();
    k_count<<<(E + 255) / 256, 256>>>(edges, E);
    k_scan<<<1, 1024>>>();
    k_fill<<<(E + 255) / 256, 256>>>(edges, E);

    // 3. two fused conv rounds (ping-pong: 0->1->0, final h in g_h[0])
    k_conv<<<NN, 64>>>(0, 1, Wc, bc);
    k_conv<<<NN, 64>>>(1, 0, Wc, bc);

    // 4. S = h h^T, both output planes
    dim3 grid(NN / 128, NN / 128);
    k_gemm<<<grid, 256>>>(nodes, out);

    (void)n_in; (void)out_size;
}

// round 2
// speedup vs baseline: 1.2212x; 1.2212x over previous
#include <cuda_runtime.h>
#include <cstdint>

#define NN 8192
#define FD 10
#define HD 64
#define EMX 524288

// Scratch (static __device__ per allocation rules)
__device__ float g_h[2][NN * HD];
__device__ int g_cnt[NN];
__device__ int g_start[NN];
__device__ int g_fill[NN];
__device__ int g_csr[EMX];

// packed fp32x2 FMA: d.lo += a.lo*b.lo ; d.hi += a.hi*b.hi (bitwise == 2 scalar fmaf)
#define FMA2(d, a, b) \
    asm("fma.rn.f32x2 %0, %1, %2, %0;" : "+l"(d) : "l"(a), "l"(b))
#define PACKDUP(d, s) \
    asm("mov.b64 %0, {%1, %1};" : "=l"(d) : "f"(s))

// ---------------------------------------------------------------------------
// h0 = relu(features @ W_node + b_node)
// ---------------------------------------------------------------------------
__global__ void k_node(const float* __restrict__ feat,
                       const float* __restrict__ Wn,
                       const float* __restrict__ bn) {
    int row = blockIdx.x;
    int t = threadIdx.x;
    __shared__ float f[FD];
    if (t < FD) f[t] = feat[row * FD + t];
    __syncthreads();
    float acc = bn[t];
#pragma unroll
    for (int k = 0; k < FD; k++) acc = fmaf(f[k], Wn[k * HD + t], acc);
    g_h[0][row * HD + t] = fmaxf(acc, 0.f);
}

// ---------------------------------------------------------------------------
// CSR build: count -> scan -> fill
// ---------------------------------------------------------------------------
__global__ void k_zero() {
    int i = blockIdx.x * blockDim.x + threadIdx.x;
    if (i < NN) g_cnt[i] = 0;
}

__global__ void k_count(const int* __restrict__ edges, int E) {
    int e = blockIdx.x * blockDim.x + threadIdx.x;
    if (e < E) atomicAdd(&g_cnt[edges[2 * e + 1]], 1);
}

// 1024 threads, 8 elems each; warp-shuffle scan (3 barriers total)
__global__ void k_scan() {
    int t = threadIdx.x;
    int lane = t & 31;
    int w = t >> 5;
    int base = t * 8;
    int loc[8];
    int s = 0;
#pragma unroll
    for (int j = 0; j < 8; j++) { loc[j] = s; s += g_cnt[base + j]; }
    // warp inclusive scan of s
    int v = s;
#pragma unroll
    for (int off = 1; off < 32; off <<= 1) {
        int u = __shfl_up_sync(0xFFFFFFFFu, v, off);
        if (lane >= off) v += u;
    }
    __shared__ int wsum[32];
    if (lane == 31) wsum[w] = v;
    __syncthreads();
    if (w == 0) {
        int x = wsum[lane];
#pragma unroll
        for (int off = 1; off < 32; off <<= 1) {
            int u = __shfl_up_sync(0xFFFFFFFFu, x, off);
            if (lane >= off) x += u;
        }
        wsum[lane] = x;
    }
    __syncthreads();
    int excl = v - s + (w ? wsum[w - 1] : 0);
#pragma unroll
    for (int j = 0; j < 8; j++) {
        int o = excl + loc[j];
        g_start[base + j] = o;
        g_fill[base + j] = o;
    }
}

__global__ void k_fill(const int* __restrict__ edges, int E) {
    int e = blockIdx.x * blockDim.x + threadIdx.x;
    if (e < E) {
        int dst = edges[2 * e + 1];
        int pos = atomicAdd(&g_fill[dst], 1);
        g_csr[pos] = edges[2 * e + 0];
    }
}

// ---------------------------------------------------------------------------
// Fused conv round
// ---------------------------------------------------------------------------
__global__ void k_conv(int ib, int ob,
                       const float* __restrict__ Wc,
                       const float* __restrict__ bc) {
    const float* __restrict__ hin = g_h[ib];
    float* __restrict__ hout = g_h[ob];
    int i = blockIdx.x;
    int t = threadIdx.x;
    int s0 = g_start[i];
    int c = g_cnt[i];
    float a0 = 0.f, a1 = 0.f, a2 = 0.f, a3 = 0.f;
    int e = 0;
    for (; e + 4 <= c; e += 4) {
        int i0 = g_csr[s0 + e + 0];
        int i1 = g_csr[s0 + e + 1];
        int i2 = g_csr[s0 + e + 2];
        int i3 = g_csr[s0 + e + 3];
        a0 += hin[i0 * HD + t];
        a1 += hin[i1 * HD + t];
        a2 += hin[i2 * HD + t];
        a3 += hin[i3 * HD + t];
    }
    for (; e < c; e++) a0 += hin[g_csr[s0 + e] * HD + t];

    __shared__ float x[HD];
    x[t] = hin[i * HD + t] + ((a0 + a1) + (a2 + a3));
    __syncthreads();

    float acc = bc[t];
#pragma unroll
    for (int k = 0; k < HD; k++) acc = fmaf(x[k], Wc[k * HD + t], acc);
    hout[i * HD + t] = fmaxf(acc, 0.f);
}

// ---------------------------------------------------------------------------
// S = h @ h^T (symmetric): only upper-triangular 128x128 tiles, mirror-write.
// k-major smem so b-pairs are contiguous for fma.rn.f32x2.
// ---------------------------------------------------------------------------
__global__ __launch_bounds__(256, 2) void k_gemm(const int* __restrict__ nodes,
                                                 float* __restrict__ out) {
    const float* __restrict__ h = g_h[0];
    __shared__ float As[32][132];   // [k][row]
    __shared__ float Bs[32][132];   // [k][col]

    // triangular decode: bid -> (bx >= by)
    int bid = blockIdx.x;
    int p = (int)((sqrtf(8.f * (float)bid + 1.f) - 1.f) * 0.5f);
    while ((p + 1) * (p + 2) / 2 <= bid) p++;
    while (p * (p + 1) / 2 > bid) p--;
    int bx = p;
    int by = bid - p * (p + 1) / 2;
    int row0 = by * 128;
    int col0 = bx * 128;

    int tid = threadIdx.x;
    int tx = tid & 15;   // cols tx*4.. and 64+tx*4..
    int ty = tid >> 4;   // rows ty*4.. and 64+ty*4..

    union AccU {
        uint64_t u[8][4];
        float f[8][8];    // f[i][2*jp+h] == halves of u[i][jp]
    } acc;
#pragma unroll
    for (int i = 0; i < 8; i++)
#pragma unroll
        for (int j = 0; j < 4; j++) acc.u[i][j] = 0ull;

#pragma unroll
    for (int k0 = 0; k0 < HD; k0 += 32) {
        // stage 128 rows x 32 k (each matrix) transposed into smem
#pragma unroll
        for (int q = 0; q < 4; q++) {
            int idx = q * 256 + tid;      // [0,1024)
            int r = idx >> 3;             // 0..127
            int kq = idx & 7;             // float4 index within 32-k chunk
            float4 va = *reinterpret_cast<const float4*>(
                &h[(size_t)(row0 + r) * HD + k0 + kq * 4]);
            As[kq * 4 + 0][r] = va.x;
            As[kq * 4 + 1][r] = va.y;
            As[kq * 4 + 2][r] = va.z;
            As[kq * 4 + 3][r] = va.w;
            float4 vb = *reinterpret_cast<const float4*>(
                &h[(size_t)(col0 + r) * HD + k0 + kq * 4]);
            Bs[kq * 4 + 0][r] = vb.x;
            Bs[kq * 4 + 1][r] = vb.y;
            Bs[kq * 4 + 2][r] = vb.z;
            Bs[kq * 4 + 3][r] = vb.w;
        }
        __syncthreads();

#pragma unroll 8
        for (int k = 0; k < 32; k++) {
            const float* ar = As[k];
            const float* br = Bs[k];
            float4 av0 = *reinterpret_cast<const float4*>(ar + ty * 4);
            float4 av1 = *reinterpret_cast<const float4*>(ar + 64 + ty * 4);
            uint64_t b0 = *reinterpret_cast<const uint64_t*>(br + tx * 4);
            uint64_t b1 = *reinterpret_cast<const uint64_t*>(br + tx * 4 + 2);
            uint64_t b2 = *reinterpret_cast<const uint64_t*>(br + 64 + tx * 4);
            uint64_t b3 = *reinterpret_cast<const uint64_t*>(br + 64 + tx * 4 + 2);
            uint64_t a2;
            PACKDUP(a2, av0.x);
            FMA2(acc.u[0][0], a2, b0); FMA2(acc.u[0][1], a2, b1);
            FMA2(acc.u[0][2], a2, b2); FMA2(acc.u[0][3], a2, b3);
            PACKDUP(a2, av0.y);
            FMA2(acc.u[1][0], a2, b0); FMA2(acc.u[1][1], a2, b1);
            FMA2(acc.u[1][2], a2, b2); FMA2(acc.u[1][3], a2, b3);
            PACKDUP(a2, av0.z);
            FMA2(acc.u[2][0], a2, b0); FMA2(acc.u[2][1], a2, b1);
            FMA2(acc.u[2][2], a2, b2); FMA2(acc.u[2][3], a2, b3);
            PACKDUP(a2, av0.w);
            FMA2(acc.u[3][0], a2, b0); FMA2(acc.u[3][1], a2, b1);
            FMA2(acc.u[3][2], a2, b2); FMA2(acc.u[3][3], a2, b3);
            PACKDUP(a2, av1.x);
            FMA2(acc.u[4][0], a2, b0); FMA2(acc.u[4][1], a2, b1);
            FMA2(acc.u[4][2], a2, b2); FMA2(acc.u[4][3], a2, b3);
            PACKDUP(a2, av1.y);
            FMA2(acc.u[5][0], a2, b0); FMA2(acc.u[5][1], a2, b1);
            FMA2(acc.u[5][2], a2, b2); FMA2(acc.u[5][3], a2, b3);
            PACKDUP(a2, av1.z);
            FMA2(acc.u[6][0], a2, b0); FMA2(acc.u[6][1], a2, b1);
            FMA2(acc.u[6][2], a2, b2); FMA2(acc.u[6][3], a2, b3);
            PACKDUP(a2, av1.w);
            FMA2(acc.u[7][0], a2, b0); FMA2(acc.u[7][1], a2, b1);
            FMA2(acc.u[7][2], a2, b2); FMA2(acc.u[7][3], a2, b3);
        }
        __syncthreads();
    }

    // masks; acc.f[i][j]: j<4 -> col tx*4+j ; j>=4 -> col 64+tx*4+(j-4)
    float mr[8], mc[8];
#pragma unroll
    for (int i = 0; i < 8; i++) {
        int ri = (i < 4) ? (ty * 4 + i) : (64 + ty * 4 + (i - 4));
        mr[i] = (nodes[row0 + ri] == 2) ? 1.f : 0.f;
    }
#pragma unroll
    for (int j = 0; j < 8; j++) {
        int cj = (j < 4) ? (tx * 4 + j) : (64 + tx * 4 + (j - 4));
        mc[j] = (nodes[col0 + cj] == 2) ? 1.f : 0.f;
    }

    float* out_dep = out;
    float* out_sim = out + (size_t)NN * NN;

    // direct tile writes
#pragma unroll
    for (int i = 0; i < 8; i++) {
        int ri = (i < 4) ? (ty * 4 + i) : (64 + ty * 4 + (i - 4));
        size_t base = (size_t)(row0 + ri) * NN + col0;
        float4 s0 = make_float4(acc.f[i][0], acc.f[i][1], acc.f[i][2], acc.f[i][3]);
        float4 s1 = make_float4(acc.f[i][4], acc.f[i][5], acc.f[i][6], acc.f[i][7]);
        *reinterpret_cast<float4*>(&out_sim[base + tx * 4]) = s0;
        *reinterpret_cast<float4*>(&out_sim[base + 64 + tx * 4]) = s1;
        float mi = mr[i];
        float4 d0 = make_float4(acc.f[i][0] * mi * mc[0], acc.f[i][1] * mi * mc[1],
                                acc.f[i][2] * mi * mc[2], acc.f[i][3] * mi * mc[3]);
        float4 d1 = make_float4(acc.f[i][4] * mi * mc[4], acc.f[i][5] * mi * mc[5],
                                acc.f[i][6] * mi * mc[6], acc.f[i][7] * mi * mc[7]);
        *reinterpret_cast<float4*>(&out_dep[base + tx * 4]) = d0;
        *reinterpret_cast<float4*>(&out_dep[base + 64 + tx * 4]) = d1;
    }

    // mirror tile writes (transpose), skip diagonal
    if (bx != by) {
#pragma unroll
        for (int j = 0; j < 8; j++) {
            int cj = (j < 4) ? (tx * 4 + j) : (64 + tx * 4 + (j - 4));
            size_t base = (size_t)(col0 + cj) * NN + row0;
            float4 s0 = make_float4(acc.f[0][j], acc.f[1][j], acc.f[2][j], acc.f[3][j]);
            float4 s1 = make_float4(acc.f[4][j], acc.f[5][j], acc.f[6][j], acc.f[7][j]);
            *reinterpret_cast<float4*>(&out_sim[base + ty * 4]) = s0;
            *reinterpret_cast<float4*>(&out_sim[base + 64 + ty * 4]) = s1;
            float mj = mc[j];
            float4 d0 = make_float4(acc.f[0][j] * mj * mr[0], acc.f[1][j] * mj * mr[1],
                                    acc.f[2][j] * mj * mr[2], acc.f[3][j] * mj * mr[3]);
            float4 d1 = make_float4(acc.f[4][j] * mj * mr[4], acc.f[5][j] * mj * mr[5],
                                    acc.f[6][j] * mj * mr[6], acc.f[7][j] * mj * mr[7]);
            *reinterpret_cast<float4*>(&out_dep[base + ty * 4]) = d0;
            *reinterpret_cast<float4*>(&out_dep[base + 64 + ty * 4]) = d1;
        }
    }
}

// ---------------------------------------------------------------------------
extern "C" void kernel_launch(void* const* d_in, const int* in_sizes, int n_in,
                              void* d_out, int out_size) {
    const float* feat = (const float*)d_in[0];
    const float* Wn   = (const float*)d_in[1];
    const float* bn   = (const float*)d_in[2];
    const float* Wc   = (const float*)d_in[3];
    const float* bc   = (const float*)d_in[4];
    const int* nodes  = (const int*)d_in[5];
    const int* edges  = (const int*)d_in[6];
    int E = in_sizes[6] / 2;
    float* out = (float*)d_out;

    k_node<<<NN, 64>>>(feat, Wn, bn);

    k_zero<<<(NN + 255) / 256, 256>>>();
    k_count<<<(E + 255) / 256, 256>>>(edges, E);
    k_scan<<<1, 1024>>>();
    k_fill<<<(E + 255) / 256, 256>>>(edges, E);

    k_conv<<<NN, 64>>>(0, 1, Wc, bc);
    k_conv<<<NN, 64>>>(1, 0, Wc, bc);

    int ntiles = (NN / 128) * (NN / 128 + 1) / 2;   // 2080
    k_gemm<<<ntiles, 256>>>(nodes, out);

    (void)n_in; (void)out_size;
}

// round 4
// speedup vs baseline: 1.5143x; 1.2400x over previous
#include <cuda_runtime.h>
#include <cuda_bf16.h>
#include <cstdint>

#define NN 8192
#define FD 10
#define HD 64
#define EMX 524288

// Scratch (static __device__ per allocation rules)
__device__ float g_h[2][NN * HD];
__device__ __nv_bfloat16 g_hi[NN * HD];
__device__ __nv_bfloat16 g_lo[NN * HD];
__device__ int g_cnt[NN];
__device__ int g_start[NN];
__device__ int g_fill[NN];
__device__ int g_csr[EMX];

// ---------------------------------------------------------------------------
// helpers
// ---------------------------------------------------------------------------
__device__ __forceinline__ uint32_t smem_u32(const void* p) {
    uint32_t a;
    asm("{ .reg .u64 t; cvta.to.shared.u64 t, %1; cvt.u32.u64 %0, t; }"
        : "=r"(a) : "l"(p));
    return a;
}

__device__ __forceinline__ void ldm_x4(uint32_t* r, uint32_t addr) {
    asm volatile("ldmatrix.sync.aligned.m8n8.x4.shared.b16 {%0,%1,%2,%3}, [%4];"
                 : "=r"(r[0]), "=r"(r[1]), "=r"(r[2]), "=r"(r[3]) : "r"(addr));
}
__device__ __forceinline__ void ldm_x2(uint32_t* r, uint32_t addr) {
    asm volatile("ldmatrix.sync.aligned.m8n8.x2.shared.b16 {%0,%1}, [%2];"
                 : "=r"(r[0]), "=r"(r[1]) : "r"(addr));
}
__device__ __forceinline__ void mma_bf16(float* c, const uint32_t* a,
                                         const uint32_t* b) {
    asm volatile(
        "mma.sync.aligned.m16n8k16.row.col.f32.bf16.bf16.f32 "
        "{%0,%1,%2,%3}, {%4,%5,%6,%7}, {%8,%9}, {%0,%1,%2,%3};"
        : "+f"(c[0]), "+f"(c[1]), "+f"(c[2]), "+f"(c[3])
        : "r"(a[0]), "r"(a[1]), "r"(a[2]), "r"(a[3]), "r"(b[0]), "r"(b[1]));
}

#define SWZ(bo) ((bo) ^ (((bo) >> 3) & 0x70))

// ---------------------------------------------------------------------------
// h0 = relu(features @ W_node + b_node)
// ---------------------------------------------------------------------------
__global__ void k_node(const float* __restrict__ feat,
                       const float* __restrict__ Wn,
                       const float* __restrict__ bn) {
    int row = blockIdx.x;
    int t = threadIdx.x;
    __shared__ float f[FD];
    if (t < FD) f[t] = feat[row * FD + t];
    __syncthreads();
    float acc = bn[t];
#pragma unroll
    for (int k = 0; k < FD; k++) acc = fmaf(f[k], Wn[k * HD + t], acc);
    g_h[0][row * HD + t] = fmaxf(acc, 0.f);
}

// ---------------------------------------------------------------------------
// CSR build
// ---------------------------------------------------------------------------
__global__ void k_zero() {
    int i = blockIdx.x * blockDim.x + threadIdx.x;
    if (i < NN) g_cnt[i] = 0;
}

__global__ void k_count(const int* __restrict__ edges, int E) {
    int e = blockIdx.x * blockDim.x + threadIdx.x;
    if (e < E) atomicAdd(&g_cnt[edges[2 * e + 1]], 1);
}

__global__ void k_scan() {
    int t = threadIdx.x;
    int lane = t & 31;
    int w = t >> 5;
    int base = t * 8;
    int loc[8];
    int s = 0;
#pragma unroll
    for (int j = 0; j < 8; j++) { loc[j] = s; s += g_cnt[base + j]; }
    int v = s;
#pragma unroll
    for (int off = 1; off < 32; off <<= 1) {
        int u = __shfl_up_sync(0xFFFFFFFFu, v, off);
        if (lane >= off) v += u;
    }
    __shared__ int wsum[32];
    if (lane == 31) wsum[w] = v;
    __syncthreads();
    if (w == 0) {
        int x = wsum[lane];
#pragma unroll
        for (int off = 1; off < 32; off <<= 1) {
            int u = __shfl_up_sync(0xFFFFFFFFu, x, off);
            if (lane >= off) x += u;
        }
        wsum[lane] = x;
    }
    __syncthreads();
    int excl = v - s + (w ? wsum[w - 1] : 0);
#pragma unroll
    for (int j = 0; j < 8; j++) {
        int o = excl + loc[j];
        g_start[base + j] = o;
        g_fill[base + j] = o;
    }
}

__global__ void k_fill(const int* __restrict__ edges, int E) {
    int e = blockIdx.x * blockDim.x + threadIdx.x;
    if (e < E) {
        int dst = edges[2 * e + 1];
        int pos = atomicAdd(&g_fill[dst], 1);
        g_csr[pos] = edges[2 * e + 0];
    }
}

// ---------------------------------------------------------------------------
// Fused conv round
// ---------------------------------------------------------------------------
__global__ void k_conv(int ib, int ob,
                       const float* __restrict__ Wc,
                       const float* __restrict__ bc) {
    const float* __restrict__ hin = g_h[ib];
    float* __restrict__ hout = g_h[ob];
    int i = blockIdx.x;
    int t = threadIdx.x;
    int s0 = g_start[i];
    int c = g_cnt[i];
    float a0 = 0.f, a1 = 0.f, a2 = 0.f, a3 = 0.f;
    int e = 0;
    for (; e + 4 <= c; e += 4) {
        int i0 = g_csr[s0 + e + 0];
        int i1 = g_csr[s0 + e + 1];
        int i2 = g_csr[s0 + e + 2];
        int i3 = g_csr[s0 + e + 3];
        a0 += hin[i0 * HD + t];
        a1 += hin[i1 * HD + t];
        a2 += hin[i2 * HD + t];
        a3 += hin[i3 * HD + t];
    }
    for (; e < c; e++) a0 += hin[g_csr[s0 + e] * HD + t];

    __shared__ float x[HD];
    x[t] = hin[i * HD + t] + ((a0 + a1) + (a2 + a3));
    __syncthreads();

    float acc = bc[t];
#pragma unroll
    for (int k = 0; k < HD; k++) acc = fmaf(x[k], Wc[k * HD + t], acc);
    hout[i * HD + t] = fmaxf(acc, 0.f);
}

// ---------------------------------------------------------------------------
// Split h into bf16 hi/lo
// ---------------------------------------------------------------------------
__global__ void k_cvt() {
    int i = blockIdx.x * blockDim.x + threadIdx.x;
    float v = g_h[0][i];
    __nv_bfloat16 hi = __float2bfloat16(v);
    g_hi[i] = hi;
    g_lo[i] = __float2bfloat16(v - __bfloat162float(hi));
}

// ---------------------------------------------------------------------------
// mma.sync GEMM: 128x128 tile per CTA, K=64, bf16-split 3 terms, fp32 acc.
// 8 warps: 2 (m, 64 rows) x 4 (n, 32 cols). Warp tile 64x32 = 4 m16 x 4 n8.
// smem: Ahi/Alo/Bhi/Blo tiles 128x64 bf16, SW128 swizzled (row = 128B atom).
// ---------------------------------------------------------------------------
#define SM_AH 0
#define SM_AL 16384
#define SM_BH 32768
#define SM_BL 49152
#define SM_TOTAL 65536

__global__ void __launch_bounds__(256) k_tgemm(const int* __restrict__ nodes,
                                               float* __restrict__ out) {
    extern __shared__ char smem[];
    uint32_t sb = smem_u32(smem);
    int tid = threadIdx.x;
    int lane = tid & 31;
    int w = tid >> 5;
    int wm = w >> 2;   // 0..1
    int wn = w & 3;    // 0..3

    int row0 = blockIdx.y * 128;
    int col0 = blockIdx.x * 128;

    // ---- stage 4 tiles (each contiguous 16KB in gmem: 128 rows x 128B) ----
    const char* pAH = (const char*)g_hi + (size_t)row0 * 128;
    const char* pAL = (const char*)g_lo + (size_t)row0 * 128;
    const char* pBH = (const char*)g_hi + (size_t)col0 * 128;
    const char* pBL = (const char*)g_lo + (size_t)col0 * 128;
#pragma unroll
    for (int q = 0; q < 4; q++) {
        int u = q * 256 + tid;   // 0..1023
        int bo = u * 16;
        int sw = SWZ(bo);
        *(uint4*)(smem + SM_AH + sw) = *(const uint4*)(pAH + bo);
        *(uint4*)(smem + SM_AL + sw) = *(const uint4*)(pAL + bo);
        *(uint4*)(smem + SM_BH + sw) = *(const uint4*)(pBH + bo);
        *(uint4*)(smem + SM_BL + sw) = *(const uint4*)(pBL + bo);
    }
    __syncthreads();

    // ---- accumulators ----
    float acc[4][4][4];
#pragma unroll
    for (int i = 0; i < 4; i++)
#pragma unroll
        for (int j = 0; j < 4; j++)
#pragma unroll
            for (int c = 0; c < 4; c++) acc[i][j][c] = 0.f;

    // per-lane ldmatrix row indices
    int a_row_in_tile = (lane & 7) + 8 * ((lane >> 3) & 1);  // 0..15
    int a_kk_half = (lane >> 4);                              // 0/1 -> k+0/k+8
    int l16 = lane & 15;
    int b_col_in_tile = l16 & 7;                              // 0..7
    int b_kk_half = l16 >> 3;                                 // 0/1

#pragma unroll
    for (int ks = 0; ks < 4; ks++) {
        int k0 = ks * 16;
        uint32_t aH[4][4], aL[4][4], bH[4][2], bL[4][2];
#pragma unroll
        for (int mt = 0; mt < 4; mt++) {
            int r = wm * 64 + mt * 16 + a_row_in_tile;
            int bo = r * 128 + (k0 + 8 * a_kk_half) * 2;
            int sw = SWZ(bo);
            ldm_x4(aH[mt], sb + SM_AH + sw);
            ldm_x4(aL[mt], sb + SM_AL + sw);
        }
#pragma unroll
        for (int nt = 0; nt < 4; nt++) {
            int cgl = wn * 32 + nt * 8 + b_col_in_tile;
            int bo = cgl * 128 + (k0 + 8 * b_kk_half) * 2;
            int sw = SWZ(bo);
            ldm_x2(bH[nt], sb + SM_BH + sw);
            ldm_x2(bL[nt], sb + SM_BL + sw);
        }
#pragma unroll
        for (int mt = 0; mt < 4; mt++)
#pragma unroll
            for (int nt = 0; nt < 4; nt++) {
                mma_bf16(acc[mt][nt], aH[mt], bH[nt]);
                mma_bf16(acc[mt][nt], aH[mt], bL[nt]);
                mma_bf16(acc[mt][nt], aL[mt], bH[nt]);
            }
    }
    // no trailing __syncthreads needed (smem not reused)

    // ---- masks ----
    // rows this thread stores: wm*64 + mt*16 + lane/4 (+8)
    float mr[4][2];
#pragma unroll
    for (int mt = 0; mt < 4; mt++) {
        int r = row0 + wm * 64 + mt * 16 + (lane >> 2);
        mr[mt][0] = (nodes[r] == 2) ? 1.f : 0.f;
        mr[mt][1] = (nodes[r + 8] == 2) ? 1.f : 0.f;
    }
    // cols: wn*32 + nt*8 + 2*(lane&3) and +1
    float mc[4][2];
#pragma unroll
    for (int nt = 0; nt < 4; nt++) {
        int c = col0 + wn * 32 + nt * 8 + 2 * (lane & 3);
        mc[nt][0] = (nodes[c] == 2) ? 1.f : 0.f;
        mc[nt][1] = (nodes[c + 1] == 2) ? 1.f : 0.f;
    }

    float* out_dep = out;
    float* out_sim = out + (size_t)NN * NN;

#pragma unroll
    for (int mt = 0; mt < 4; mt++) {
        int r0 = row0 + wm * 64 + mt * 16 + (lane >> 2);
        int r1 = r0 + 8;
#pragma unroll
        for (int nt = 0; nt < 4; nt++) {
            int c = col0 + wn * 32 + nt * 8 + 2 * (lane & 3);
            const float* a4 = acc[mt][nt];
            float2 s0 = make_float2(a4[0], a4[1]);
            float2 s1 = make_float2(a4[2], a4[3]);
            *(float2*)&out_sim[(size_t)r0 * NN + c] = s0;
            *(float2*)&out_sim[(size_t)r1 * NN + c] = s1;
            float2 d0 = make_float2(a4[0] * mr[mt][0] * mc[nt][0],
                                    a4[1] * mr[mt][0] * mc[nt][1]);
            float2 d1 = make_float2(a4[2] * mr[mt][1] * mc[nt][0],
                                    a4[3] * mr[mt][1] * mc[nt][1]);
            *(float2*)&out_dep[(size_t)r0 * NN + c] = d0;
            *(float2*)&out_dep[(size_t)r1 * NN + c] = d1;
        }
    }
}

// ---------------------------------------------------------------------------
extern "C" void kernel_launch(void* const* d_in, const int* in_sizes, int n_in,
                              void* d_out, int out_size) {
    const float* feat = (const float*)d_in[0];
    const float* Wn   = (const float*)d_in[1];
    const float* bn   = (const float*)d_in[2];
    const float* Wc   = (const float*)d_in[3];
    const float* bc   = (const float*)d_in[4];
    const int* nodes  = (const int*)d_in[5];
    const int* edges  = (const int*)d_in[6];
    int E = in_sizes[6] / 2;
    float* out = (float*)d_out;

    k_node<<<NN, 64>>>(feat, Wn, bn);

    k_zero<<<(NN + 255) / 256, 256>>>();
    k_count<<<(E + 255) / 256, 256>>>(edges, E);
    k_scan<<<1, 1024>>>();
    k_fill<<<(E + 255) / 256, 256>>>(edges, E);

    k_conv<<<NN, 64>>>(0, 1, Wc, bc);
    k_conv<<<NN, 64>>>(1, 0, Wc, bc);

    k_cvt<<<NN * HD / 256, 256>>>();

    cudaFuncSetAttribute(k_tgemm, cudaFuncAttributeMaxDynamicSharedMemorySize,
                         SM_TOTAL);
    dim3 grid(NN / 128, NN / 128);
    k_tgemm<<<grid, 256, SM_TOTAL>>>(nodes, out);

    (void)n_in; (void)out_size;
}